// round 3
// baseline (speedup 1.0000x reference)
#include <cuda_runtime.h>

// ---------------------------------------------------------------------------
// CurveChannel, single fused kernel.
// out[b,0,h,w] = clamp( sum_c sum_p conv_w[c]*slopes[p,c]*relu(x[b,c,h,w]
//                       - shift[p,c]) + conv_b, 0, 1 )
//
// Thread 0 of each block folds conv_w into slopes and compacts the nonzero
// breakpoints (1/channel in this dataset) into shared, overlapped with the
// other warps' x loads (single barrier). Each thread handles 2 float4 groups
// -> 6 independent LDG.128 in flight at ~45 regs, preserving high occupancy.
// ---------------------------------------------------------------------------

#define NPTS   16
#define IN_CH  3
#define HW4    (512 * 512 / 4)      // float4 groups per (b,c) plane = 65536
#define GPT    2                    // groups per thread
#define TPB    256
#define GPB    (GPT * TPB)          // 512
#define BLKS_PER_BATCH (HW4 / GPB)  // 128

__global__ __launch_bounds__(TPB) void curve_fused(
    const float* __restrict__ x,       // (8, 3, 512, 512)
    const float* __restrict__ shift,   // (NPTS, C)
    const float* __restrict__ slopes,  // (NPTS, C)
    const float* __restrict__ conv_w,  // (C,)
    const float* __restrict__ conv_b,  // (1,)
    float* __restrict__ out)           // (8, 1, 512, 512)
{
    __shared__ int   s_cnt[IN_CH];
    __shared__ float s_shift[IN_CH][NPTS];
    __shared__ float s_ws[IN_CH][NPTS];
    __shared__ float s_bias;

    const int tid = threadIdx.x;

    // ---- issue all x loads first: independent of the params ----
    const int b  = blockIdx.x / BLKS_PER_BATCH;
    const int bg = (blockIdx.x % BLKS_PER_BATCH) * GPB;
    const float4* xb = reinterpret_cast<const float4*>(x) +
                       (size_t)b * (IN_CH * HW4) + bg + tid;

    float4 xv[IN_CH][GPT];
    #pragma unroll
    for (int c = 0; c < IN_CH; ++c)
        #pragma unroll
        for (int u = 0; u < GPT; ++u)
            xv[c][u] = __ldg(&xb[c * HW4 + u * TPB]);

    // ---- thread 0 compacts params while the loads are in flight ----
    if (tid == 0) {
        #pragma unroll
        for (int c = 0; c < IN_CH; ++c) {
            const float w = __ldg(&conv_w[c]);
            int n = 0;
            #pragma unroll
            for (int p = 0; p < NPTS; ++p) {
                const float s = __ldg(&slopes[p * IN_CH + c]);
                if (s != 0.0f) {
                    s_shift[c][n] = __ldg(&shift[p * IN_CH + c]);
                    s_ws[c][n]    = s * w;
                    ++n;
                }
            }
            s_cnt[c] = n;
        }
        s_bias = __ldg(&conv_b[0]);
    }
    __syncthreads();

    const float bias = s_bias;
    float4 acc[GPT];
    #pragma unroll
    for (int u = 0; u < GPT; ++u)
        acc[u] = make_float4(bias, bias, bias, bias);

    #pragma unroll
    for (int c = 0; c < IN_CH; ++c) {
        const int n = s_cnt[c];
        #pragma unroll 1
        for (int j = 0; j < n; ++j) {
            const float sh = s_shift[c][j];
            const float w  = s_ws[c][j];
            #pragma unroll
            for (int u = 0; u < GPT; ++u) {
                acc[u].x = fmaf(w, fmaxf(xv[c][u].x - sh, 0.0f), acc[u].x);
                acc[u].y = fmaf(w, fmaxf(xv[c][u].y - sh, 0.0f), acc[u].y);
                acc[u].z = fmaf(w, fmaxf(xv[c][u].z - sh, 0.0f), acc[u].z);
                acc[u].w = fmaf(w, fmaxf(xv[c][u].w - sh, 0.0f), acc[u].w);
            }
        }
    }

    float4* ob = reinterpret_cast<float4*>(out) + (size_t)b * HW4 + bg + tid;
    #pragma unroll
    for (int u = 0; u < GPT; ++u) {
        float4 a = acc[u];
        a.x = fminf(fmaxf(a.x, 0.0f), 1.0f);
        a.y = fminf(fmaxf(a.y, 0.0f), 1.0f);
        a.z = fminf(fmaxf(a.z, 0.0f), 1.0f);
        a.w = fminf(fmaxf(a.w, 0.0f), 1.0f);
        ob[u * TPB] = a;
    }
}

extern "C" void kernel_launch(void* const* d_in, const int* in_sizes, int n_in,
                              void* d_out, int out_size)
{
    const float* x      = (const float*)d_in[0];
    const float* shift  = (const float*)d_in[1];
    const float* slopes = (const float*)d_in[2];
    const float* conv_w = (const float*)d_in[3];
    const float* conv_b = (const float*)d_in[4];
    float* out = (float*)d_out;

    const int total_groups = out_size / 4;   // 524288
    const int blocks = total_groups / GPB;   // 1024
    curve_fused<<<blocks, TPB>>>(x, shift, slopes, conv_w, conv_b, out);
}

// round 4
// speedup vs baseline: 1.4723x; 1.4723x over previous
#include <cuda_runtime.h>

// ---------------------------------------------------------------------------
// CurveChannel, single kernel, barrier-free.
// out[b,0,h,w] = clamp( sum_c sum_p conv_w[c]*slopes[p,c]*relu(x[b,c,h,w]
//                       - shift[p,c]) + conv_b, 0, 1 )
//
// Warp-level param compaction: lane p (<16) holds slopes[p,c]/shift[p,c];
// ballot(slope != 0) -> active-point mask; consume loop shfl-broadcasts each
// active point. No shared memory, no __syncthreads, no helper launch. The
// three x LDG.128 are front-batched and independent (true MLP=3/thread),
// with the tiny param loads issued first.
// ---------------------------------------------------------------------------

#define NPTS   16
#define IN_CH  3
#define HW4    (512 * 512 / 4)   // float4 groups per (b,c) plane = 65536
#define TPB    256

__global__ __launch_bounds__(TPB) void curve_fused(
    const float* __restrict__ x,       // (8, 3, 512, 512)
    const float* __restrict__ shift,   // (NPTS, C)
    const float* __restrict__ slopes,  // (NPTS, C)
    const float* __restrict__ conv_w,  // (C,)
    const float* __restrict__ conv_b,  // (1,)
    float* __restrict__ out)           // (8, 1, 512, 512)
{
    const int tid  = threadIdx.x;
    const int lane = tid & 31;

    // ---- param loads first (few cache lines, warp-coalesced) ----
    float my_sl[IN_CH], my_sh[IN_CH];
    const bool pl = (lane < NPTS);
    #pragma unroll
    for (int c = 0; c < IN_CH; ++c) {
        my_sl[c] = pl ? __ldg(&slopes[lane * IN_CH + c]) : 0.0f;
        my_sh[c] = pl ? __ldg(&shift [lane * IN_CH + c]) : 0.0f;
    }
    const float w0   = __ldg(&conv_w[0]);
    const float w1   = __ldg(&conv_w[1]);
    const float w2   = __ldg(&conv_w[2]);
    const float bias = __ldg(&conv_b[0]);

    // ---- front-batch the three independent x loads ----
    const int g = blockIdx.x * TPB + tid;     // [0, 8*HW4)
    const int b = g >> 16;                    // g / HW4
    const int v = g & (HW4 - 1);              // g % HW4
    const float4* xb = reinterpret_cast<const float4*>(x) +
                       (size_t)b * (IN_CH * HW4) + v;

    float4 xv0 = __ldg(&xb[0 * HW4]);
    float4 xv1 = __ldg(&xb[1 * HW4]);
    float4 xv2 = __ldg(&xb[2 * HW4]);

    // ---- active-point masks (overlaps x-load latency) ----
    unsigned m0 = __ballot_sync(0xFFFFFFFFu, my_sl[0] != 0.0f);
    unsigned m1 = __ballot_sync(0xFFFFFFFFu, my_sl[1] != 0.0f);
    unsigned m2 = __ballot_sync(0xFFFFFFFFu, my_sl[2] != 0.0f);

    float4 acc = make_float4(bias, bias, bias, bias);

    // channel 0
    while (m0) {
        int src = __ffs(m0) - 1; m0 &= m0 - 1;
        float sh = __shfl_sync(0xFFFFFFFFu, my_sh[0], src);
        float ws = __shfl_sync(0xFFFFFFFFu, my_sl[0], src) * w0;
        acc.x = fmaf(ws, fmaxf(xv0.x - sh, 0.0f), acc.x);
        acc.y = fmaf(ws, fmaxf(xv0.y - sh, 0.0f), acc.y);
        acc.z = fmaf(ws, fmaxf(xv0.z - sh, 0.0f), acc.z);
        acc.w = fmaf(ws, fmaxf(xv0.w - sh, 0.0f), acc.w);
    }
    // channel 1
    while (m1) {
        int src = __ffs(m1) - 1; m1 &= m1 - 1;
        float sh = __shfl_sync(0xFFFFFFFFu, my_sh[1], src);
        float ws = __shfl_sync(0xFFFFFFFFu, my_sl[1], src) * w1;
        acc.x = fmaf(ws, fmaxf(xv1.x - sh, 0.0f), acc.x);
        acc.y = fmaf(ws, fmaxf(xv1.y - sh, 0.0f), acc.y);
        acc.z = fmaf(ws, fmaxf(xv1.z - sh, 0.0f), acc.z);
        acc.w = fmaf(ws, fmaxf(xv1.w - sh, 0.0f), acc.w);
    }
    // channel 2
    while (m2) {
        int src = __ffs(m2) - 1; m2 &= m2 - 1;
        float sh = __shfl_sync(0xFFFFFFFFu, my_sh[2], src);
        float ws = __shfl_sync(0xFFFFFFFFu, my_sl[2], src) * w2;
        acc.x = fmaf(ws, fmaxf(xv2.x - sh, 0.0f), acc.x);
        acc.y = fmaf(ws, fmaxf(xv2.y - sh, 0.0f), acc.y);
        acc.z = fmaf(ws, fmaxf(xv2.z - sh, 0.0f), acc.z);
        acc.w = fmaf(ws, fmaxf(xv2.w - sh, 0.0f), acc.w);
    }

    acc.x = fminf(fmaxf(acc.x, 0.0f), 1.0f);
    acc.y = fminf(fmaxf(acc.y, 0.0f), 1.0f);
    acc.z = fminf(fmaxf(acc.z, 0.0f), 1.0f);
    acc.w = fminf(fmaxf(acc.w, 0.0f), 1.0f);

    reinterpret_cast<float4*>(out)[g] = acc;
}

extern "C" void kernel_launch(void* const* d_in, const int* in_sizes, int n_in,
                              void* d_out, int out_size)
{
    const float* x      = (const float*)d_in[0];
    const float* shift  = (const float*)d_in[1];
    const float* slopes = (const float*)d_in[2];
    const float* conv_w = (const float*)d_in[3];
    const float* conv_b = (const float*)d_in[4];
    float* out = (float*)d_out;

    const int total_groups = out_size / 4;    // 524288
    const int blocks = total_groups / TPB;    // 2048
    curve_fused<<<blocks, TPB>>>(x, shift, slopes, conv_w, conv_b, out);
}